// round 5
// baseline (speedup 1.0000x reference)
#include <cuda_runtime.h>

// Merton jump diffusion, barrier-free per-warp version with SMEM micro-transpose:
//   paths[p,0]   = S0
//   paths[p,t+1] = S0 * exp( sum_{u<=t} drift[u] + CDIFF*zd[u,p] + sqrtJ(nj[u,p])*zj[u,p] )
// Each warp owns 32 paths; the 32x32 output tile is transposed through a
// per-warp private SMEM buffer (syncwarp only, no __syncthreads in the loop).

#define N_STEPS   2048
#define N_PATHS   32768
#define TPB       64
#define WARPS     (TPB / 32)
#define TILE      32
#define N_CHUNKS  (N_STEPS / TILE)
#define OUT_COLS  (N_STEPS + 1)
#define JT_SIZE   32
#define ROWPAD    36                    // floats per row: STS.128-aligned, conflict-free

__global__ __launch_bounds__(TPB) void merton_kernel(
    const float* __restrict__ S0p,
    const float* __restrict__ zd,
    const float* __restrict__ zj,
    const int*   __restrict__ njp,
    float*       __restrict__ out)
{
    __shared__ float drift_s[N_STEPS];               // 8 KB, broadcast reads
    __shared__ float jtab[JT_SIZE];
    __shared__ float tbuf[WARPS][TILE][ROWPAD];      // 9.2 KB per-warp transpose tiles

    const int tid   = threadIdx.x;
    const int lane  = tid & 31;
    const int warp  = tid >> 5;
    const int wbase = blockIdx.x * TPB + warp * 32;  // warp's first path
    const int p     = wbase + lane;

    const float DT    = 1.0f / 2048.0f;
    const float KAPPA = 0.04602785990f;              // exp(0.045) - 1 (fp32)
    const float CDIFF = 0.2f * 0.02209708691f;       // SIGMA * fl(sqrt(DT)), ref fp32 order

    for (int i = tid; i < N_STEPS; i += TPB) {
        float t   = (float)i * DT;
        float lam = 0.1f + 0.9f * expf(-0.01f * t);
        drift_s[i] = (0.0f - lam * KAPPA) * DT;
    }
    if (tid < JT_SIZE) jtab[tid] = sqrtf((float)tid) * 0.3f;

    const float s0 = S0p[0];
    __syncthreads();                                 // one-time: tables ready

    out[p * OUT_COLS] = s0;                          // column 0

    // Single register buffer set: 96 batched LDGs in flight per warp
    float r1[TILE], r2[TILE];
    int   r3[TILE];

    #pragma unroll
    for (int s = 0; s < TILE; ++s) {
        const int idx = s * N_PATHS + p;
        r1[s] = __ldcs(zd + idx);
        r2[s] = __ldcs(zj + idx);
        r3[s] = __ldcs(njp + idx);
    }

    float acc = 0.0f;
    float v[TILE];

    for (int c = 0; c < N_CHUNKS; ++c) {
        const int tb = c * TILE;

        // Compute: serial fp32 scan (reference order); ex2 off the dep chain
        #pragma unroll
        for (int s = 0; s < TILE; ++s) {
            int n = r3[s];  n = (n < JT_SIZE) ? n : (JT_SIZE - 1);
            acc += drift_s[tb + s] + CDIFF * r1[s] + jtab[n] * r2[s];
            v[s] = s0 * __expf(acc);
        }

        // Prefetch next chunk NOW; loads fly during transpose + stores
        if (c + 1 < N_CHUNKS) {
            const int nb = (tb + TILE) * N_PATHS + p;
            #pragma unroll
            for (int s = 0; s < TILE; ++s) {
                const int idx = nb + s * N_PATHS;
                r1[s] = __ldcs(zd + idx);
                r2[s] = __ldcs(zj + idx);
                r3[s] = __ldcs(njp + idx);
            }
        }

        // Write own row (path = wbase+lane) as 8x STS.128: addr lane*144 + 16k -> conflict-free
        #pragma unroll
        for (int s = 0; s < TILE; s += 4) {
            float4 q = make_float4(v[s], v[s + 1], v[s + 2], v[s + 3]);
            *reinterpret_cast<float4*>(&tbuf[warp][lane][s]) = q;
        }
        __syncwarp();

        // Read transposed + store: row j, col lane -> 128B coalesced STG per j
        #pragma unroll
        for (int j = 0; j < TILE; ++j) {
            __stcs(&out[(wbase + j) * OUT_COLS + 1 + tb + lane], tbuf[warp][j][lane]);
        }
        __syncwarp();                                // WAR: drain reads before next STS
    }
}

extern "C" void kernel_launch(void* const* d_in, const int* in_sizes, int n_in,
                              void* d_out, int out_size)
{
    const float* S0 = (const float*)d_in[0];
    const float* zd = (const float*)d_in[1];
    const float* zj = (const float*)d_in[2];
    const int*   nj = (const int*)  d_in[3];
    float*       out = (float*)d_out;

    merton_kernel<<<N_PATHS / TPB, TPB>>>(S0, zd, zj, nj, out);
}